// round 1
// baseline (speedup 1.0000x reference)
#include <cuda_runtime.h>

#define D 128
#define KN 32
#define MAXB 20000

// Precomputed small tensors + aggregation scratch (device globals: no allocs allowed)
__device__ float g_u[D];
__device__ float g_v[D];
__device__ float g_M[D * D];
__device__ float g_agg[MAXB * D];

// ---------------------------------------------------------------------------
// Kernel P: precompute
//   u[d] = sum_e kernel1[d,e] * aw[e]
//   v[d] = sum_e kernel0[d,e] * aw[D+e]
//   M[d,e] = sum_j kernel1[d,j] * nw[j,e]
// grid = D+1 blocks, D threads. Blocks 0..D-1: one M row each. Block D: u,v.
// ---------------------------------------------------------------------------
__global__ void prep_kernel(const float* __restrict__ kernel0,
                            const float* __restrict__ kernel1,
                            const float* __restrict__ aw,
                            const float* __restrict__ nw) {
    int b = blockIdx.x;
    int t = threadIdx.x;
    if (b < D) {
        __shared__ float krow[D];
        krow[t] = kernel1[b * D + t];
        __syncthreads();
        float acc = 0.f;
#pragma unroll 8
        for (int j = 0; j < D; ++j) acc += krow[j] * nw[j * D + t];
        g_M[b * D + t] = acc;
    } else {
        float au = 0.f, av = 0.f;
#pragma unroll 8
        for (int e = 0; e < D; ++e) {
            au += kernel1[t * D + e] * aw[e];
            av += kernel0[t * D + e] * aw[D + e];
        }
        g_u[t] = au;
        g_v[t] = av;
    }
}

// ---------------------------------------------------------------------------
// Kernel A: per-target attention. One block (128 threads) per target node.
//   - gather 32 neighbor rows + 1 node row into smem (single global read each)
//   - scores via per-warp dot(u) reductions, + dot(node,v), leaky_relu
//   - softmax over K by warp 0
//   - agg[d] = sum_k w[k]*nf[k][d] -> scratch
// ---------------------------------------------------------------------------
__global__ __launch_bounds__(128) void attn_kernel(
    const float* __restrict__ features,
    const int* __restrict__ node,
    const int* __restrict__ neigh,
    int B) {
    __shared__ float nf[KN * D];   // 16 KB: 32 neighbor rows
    __shared__ float fnode[D];     // node row
    __shared__ float scores[KN];
    __shared__ float wts[KN];

    int b = blockIdx.x;
    if (b >= B) return;
    int tid  = threadIdx.x;
    int lane = tid & 31;
    int w    = tid >> 5;

    const float4* f4  = (const float4*)features;
    float4*       nf4 = (float4*)nf;

    // Gather 32 rows (1024 float4), 8 independent float4 loads per thread
#pragma unroll
    for (int it = 0; it < 8; ++it) {
        int i  = it * 128 + tid;            // float4 index within tile
        int k  = i >> 5;                    // 32 float4 per row
        int c  = i & 31;
        int nb = __ldg(&neigh[b * KN + k]);
        nf4[i] = f4[(size_t)nb * 32 + c];
    }
    if (tid < 32) {
        int nd = __ldg(&node[b]);
        ((float4*)fnode)[tid] = f4[(size_t)nd * 32 + tid];
    }
    __syncthreads();

    // sn = dot(node_row, v): computed redundantly in each warp
    float4 fv = ((const float4*)fnode)[lane];
    float4 vv = ((const float4*)g_v)[lane];
    float sn = fv.x * vv.x + fv.y * vv.y + fv.z * vv.z + fv.w * vv.w;
#pragma unroll
    for (int o = 16; o > 0; o >>= 1) sn += __shfl_xor_sync(0xffffffffu, sn, o);

    // scores: warp w handles rows w*8..w*8+7
    float4 uu = ((const float4*)g_u)[lane];
#pragma unroll
    for (int j = 0; j < 8; ++j) {
        int k = w * 8 + j;
        float4 x = nf4[k * 32 + lane];
        float s = x.x * uu.x + x.y * uu.y + x.z * uu.z + x.w * uu.w;
#pragma unroll
        for (int o = 16; o > 0; o >>= 1) s += __shfl_xor_sync(0xffffffffu, s, o);
        if (lane == 0) {
            float t = s + sn;
            scores[k] = (t > 0.f) ? t : 0.2f * t;   // leaky_relu alpha=0.2
        }
    }
    __syncthreads();

    // softmax over K=32 (warp 0)
    if (w == 0) {
        float sc = scores[lane];
        float m = sc;
#pragma unroll
        for (int o = 16; o > 0; o >>= 1) m = fmaxf(m, __shfl_xor_sync(0xffffffffu, m, o));
        float e = __expf(sc - m);
        float den = e;
#pragma unroll
        for (int o = 16; o > 0; o >>= 1) den += __shfl_xor_sync(0xffffffffu, den, o);
        wts[lane] = e / den;
    }
    __syncthreads();

    // weighted aggregate of raw features
    float acc = 0.f;
#pragma unroll
    for (int k = 0; k < KN; ++k) acc += wts[k] * nf[k * D + tid];
    g_agg[b * D + tid] = acc;
}

// ---------------------------------------------------------------------------
// Kernel G: out = agg @ M  ([B,128] x [128,128])
// M staged in 64KB dynamic smem per block; 8-row register tile per thread.
// agg rows staged transposed (aT[d*8+r]) so the inner loop reads two float4
// broadcasts + one coalesced Ms float per d.
// ---------------------------------------------------------------------------
__global__ __launch_bounds__(128) void out_gemm(float* __restrict__ out, int B) {
    extern __shared__ float sm[];
    float* Ms = sm;            // D*D floats (64 KB)
    float* aT = sm + D * D;    // D*8 floats  (4 KB), layout [d*8 + r]

    int tid = threadIdx.x;

    // stage M
    float4*       Ms4 = (float4*)Ms;
    const float4* gM4 = (const float4*)g_M;
#pragma unroll
    for (int it = 0; it < 32; ++it) Ms4[it * 128 + tid] = gM4[it * 128 + tid];

    int ngroups = (B + 7) >> 3;
    for (int g = blockIdx.x; g < ngroups; g += gridDim.x) {
        int r0 = g << 3;

        // coalesced load of 8 agg rows into registers
        float v[8];
#pragma unroll
        for (int r = 0; r < 8; ++r) {
            int row = r0 + r;
            v[r] = (row < B) ? g_agg[row * D + tid] : 0.f;
        }
        __syncthreads();   // previous iteration's aT reads done (also covers Ms on 1st iter)
        ((float4*)aT)[tid * 2]     = make_float4(v[0], v[1], v[2], v[3]);
        ((float4*)aT)[tid * 2 + 1] = make_float4(v[4], v[5], v[6], v[7]);
        __syncthreads();

        float acc[8] = {0.f, 0.f, 0.f, 0.f, 0.f, 0.f, 0.f, 0.f};
#pragma unroll 16
        for (int d = 0; d < D; ++d) {
            float m = Ms[d * D + tid];
            float4 a0 = ((const float4*)aT)[d * 2];       // broadcast
            float4 a1 = ((const float4*)aT)[d * 2 + 1];   // broadcast
            acc[0] += a0.x * m; acc[1] += a0.y * m;
            acc[2] += a0.z * m; acc[3] += a0.w * m;
            acc[4] += a1.x * m; acc[5] += a1.y * m;
            acc[6] += a1.z * m; acc[7] += a1.w * m;
        }
#pragma unroll
        for (int r = 0; r < 8; ++r) {
            int row = r0 + r;
            if (row < B) out[row * D + tid] = acc[r];
        }
    }
}

// ---------------------------------------------------------------------------
extern "C" void kernel_launch(void* const* d_in, const int* in_sizes, int n_in,
                              void* d_out, int out_size) {
    const float* features = (const float*)d_in[0];
    const int*   node     = (const int*)d_in[1];
    const int*   neigh    = (const int*)d_in[2];
    const float* kern0    = (const float*)d_in[3];
    const float* kern1    = (const float*)d_in[4];
    const float* aw       = (const float*)d_in[5];
    const float* nw       = (const float*)d_in[6];
    float*       out      = (float*)d_out;

    int B = in_sizes[1];          // node is [B,1]
    if (B > MAXB) B = MAXB;

    prep_kernel<<<D + 1, D>>>(kern0, kern1, aw, nw);
    attn_kernel<<<B, D>>>(features, node, neigh, B);

    static const int gemm_smem = (D * D + D * 8) * sizeof(float); // 68 KB
    cudaFuncSetAttribute(out_gemm, cudaFuncAttributeMaxDynamicSharedMemorySize, gemm_smem);
    out_gemm<<<444, D, gemm_smem>>>(out, B);
}

// round 2
// speedup vs baseline: 1.0485x; 1.0485x over previous
#include <cuda_runtime.h>

#define D 128
#define KN 32
#define MAXB 20000

__device__ float g_u[D];
__device__ float g_v[D];
__device__ float g_M[D * D];
__device__ float g_agg[MAXB * D];

// packed f32x2 FMA (Blackwell): acc = a*b + acc, lanewise on 2 packed floats
#define FMA2(acc, a, b) \
    asm("fma.rn.f32x2 %0, %1, %2, %0;" : "+l"(acc) : "l"(a), "l"(b))

// ---------------------------------------------------------------------------
// Kernel P: precompute  (grid = 128 blocks, 128 threads)
// Block b: stages nw (64KB) + kernel1 row b in smem, computes
//   M[b,:] = krow @ nw,  u[b] = dot(krow, aw[0:D]),  v[b] = dot(k0row, aw[D:2D])
// ---------------------------------------------------------------------------
__global__ __launch_bounds__(128) void prep_kernel(
    const float* __restrict__ kernel0,
    const float* __restrict__ kernel1,
    const float* __restrict__ aw,
    const float* __restrict__ nw) {
    extern __shared__ float psm[];
    float* nws  = psm;          // D*D floats (64KB)
    float* krow = psm + D * D;  // D floats

    int b = blockIdx.x;
    int t = threadIdx.x;

    krow[t] = kernel1[b * D + t];               // coalesced
    const float4* nw4  = (const float4*)nw;
    float4*       nws4 = (float4*)nws;
#pragma unroll
    for (int it = 0; it < 32; ++it)             // 4096 float4, MLP 32/thread
        nws4[it * 128 + t] = nw4[it * 128 + t];
    __syncthreads();

    float acc = 0.f;
#pragma unroll 16
    for (int j = 0; j < D; ++j)
        acc += krow[j] * nws[j * D + t];
    g_M[b * D + t] = acc;

    // u[b], v[b] via warp reductions
    if (t < 32) {
        float s = krow[t] * aw[t] + krow[t + 32] * aw[t + 32]
                + krow[t + 64] * aw[t + 64] + krow[t + 96] * aw[t + 96];
#pragma unroll
        for (int o = 16; o > 0; o >>= 1) s += __shfl_xor_sync(0xffffffffu, s, o);
        if (t == 0) g_u[b] = s;
    } else if (t < 64) {
        int l = t - 32;
        const float* k0r = kernel0 + b * D;
        float s = k0r[l] * aw[D + l] + k0r[l + 32] * aw[D + l + 32]
                + k0r[l + 64] * aw[D + l + 64] + k0r[l + 96] * aw[D + l + 96];
#pragma unroll
        for (int o = 16; o > 0; o >>= 1) s += __shfl_xor_sync(0xffffffffu, s, o);
        if (l == 0) g_v[b] = s;
    }
}

// ---------------------------------------------------------------------------
// Kernel A: per-target attention. One block (128 threads) per target node.
// ---------------------------------------------------------------------------
__global__ __launch_bounds__(128) void attn_kernel(
    const float* __restrict__ features,
    const int* __restrict__ node,
    const int* __restrict__ neigh,
    int B) {
    __shared__ float nf[KN * D];   // 16 KB: 32 neighbor rows
    __shared__ float fnode[D];
    __shared__ float scores[KN];
    __shared__ float wts[KN];
    __shared__ int   sidx[KN + 1];

    int b = blockIdx.x;
    if (b >= B) return;
    int tid  = threadIdx.x;
    int lane = tid & 31;
    int w    = tid >> 5;

    // stage indices once (breaks the per-thread idx->gather dependency chains)
    if (tid < KN) sidx[tid] = neigh[b * KN + tid];
    if (tid == KN) sidx[KN] = node[b];
    __syncthreads();

    const float4* f4  = (const float4*)features;
    float4*       nf4 = (float4*)nf;

    // Gather 32 rows (1024 float4): 8 independent float4 loads per thread
#pragma unroll
    for (int it = 0; it < 8; ++it) {
        int i  = it * 128 + tid;
        int k  = i >> 5;
        int c  = i & 31;
        nf4[i] = f4[(size_t)sidx[k] * 32 + c];
    }
    if (tid < 32) {
        ((float4*)fnode)[tid] = f4[(size_t)sidx[KN] * 32 + tid];
    }
    __syncthreads();

    // sn = dot(node_row, v), redundantly per warp
    float4 fv = ((const float4*)fnode)[lane];
    float4 vv = ((const float4*)g_v)[lane];
    float sn = fv.x * vv.x + fv.y * vv.y + fv.z * vv.z + fv.w * vv.w;
#pragma unroll
    for (int o = 16; o > 0; o >>= 1) sn += __shfl_xor_sync(0xffffffffu, sn, o);

    // scores: warp w handles rows w*8..w*8+7
    float4 uu = ((const float4*)g_u)[lane];
#pragma unroll
    for (int j = 0; j < 8; ++j) {
        int k = w * 8 + j;
        float4 x = nf4[k * 32 + lane];
        float s = x.x * uu.x + x.y * uu.y + x.z * uu.z + x.w * uu.w;
#pragma unroll
        for (int o = 16; o > 0; o >>= 1) s += __shfl_xor_sync(0xffffffffu, s, o);
        if (lane == 0) {
            float t = s + sn;
            scores[k] = (t > 0.f) ? t : 0.2f * t;   // leaky_relu alpha=0.2
        }
    }
    __syncthreads();

    // softmax over K=32 (warp 0)
    if (w == 0) {
        float sc = scores[lane];
        float m = sc;
#pragma unroll
        for (int o = 16; o > 0; o >>= 1) m = fmaxf(m, __shfl_xor_sync(0xffffffffu, m, o));
        float e = __expf(sc - m);
        float den = e;
#pragma unroll
        for (int o = 16; o > 0; o >>= 1) den += __shfl_xor_sync(0xffffffffu, den, o);
        wts[lane] = e / den;
    }
    __syncthreads();

    // weighted aggregate of raw features
    float acc = 0.f;
#pragma unroll
    for (int k = 0; k < KN; ++k) acc += wts[k] * nf[k * D + tid];
    g_agg[b * D + tid] = acc;
}

// ---------------------------------------------------------------------------
// Kernel G: out = agg @ M  ([B,128] x [128,128]) — packed f32x2 FMA inner loop
// ---------------------------------------------------------------------------
__global__ __launch_bounds__(128) void out_gemm(float* __restrict__ out, int B) {
    extern __shared__ float sm[];
    float* Ms = sm;            // D*D floats (64 KB)
    float* aT = sm + D * D;    // D*8 floats (4 KB), layout [d*8 + r]

    int tid = threadIdx.x;

    float4*       Ms4 = (float4*)Ms;
    const float4* gM4 = (const float4*)g_M;
#pragma unroll
    for (int it = 0; it < 32; ++it) Ms4[it * 128 + tid] = gM4[it * 128 + tid];

    int ngroups = (B + 7) >> 3;
    for (int g = blockIdx.x; g < ngroups; g += gridDim.x) {
        int r0 = g << 3;

        float v[8];
#pragma unroll
        for (int r = 0; r < 8; ++r) {
            int row = r0 + r;
            v[r] = (row < B) ? g_agg[row * D + tid] : 0.f;
        }
        __syncthreads();
        ((float4*)aT)[tid * 2]     = make_float4(v[0], v[1], v[2], v[3]);
        ((float4*)aT)[tid * 2 + 1] = make_float4(v[4], v[5], v[6], v[7]);
        __syncthreads();

        unsigned long long acc01 = 0ull, acc23 = 0ull, acc45 = 0ull, acc67 = 0ull;
#pragma unroll 16
        for (int d = 0; d < D; ++d) {
            float m = Ms[d * D + tid];
            unsigned long long mm;
            asm("mov.b64 %0, {%1, %1};" : "=l"(mm) : "f"(m));
            ulonglong2 p0 = *((const ulonglong2*)(aT + d * 8));       // (v0,v1),(v2,v3)
            ulonglong2 p1 = *((const ulonglong2*)(aT + d * 8 + 4));   // (v4,v5),(v6,v7)
            FMA2(acc01, p0.x, mm);
            FMA2(acc23, p0.y, mm);
            FMA2(acc45, p1.x, mm);
            FMA2(acc67, p1.y, mm);
        }

        float r_[8];
        asm("mov.b64 {%0, %1}, %2;" : "=f"(r_[0]), "=f"(r_[1]) : "l"(acc01));
        asm("mov.b64 {%0, %1}, %2;" : "=f"(r_[2]), "=f"(r_[3]) : "l"(acc23));
        asm("mov.b64 {%0, %1}, %2;" : "=f"(r_[4]), "=f"(r_[5]) : "l"(acc45));
        asm("mov.b64 {%0, %1}, %2;" : "=f"(r_[6]), "=f"(r_[7]) : "l"(acc67));
#pragma unroll
        for (int r = 0; r < 8; ++r) {
            int row = r0 + r;
            if (row < B) out[row * D + tid] = r_[r];
        }
    }
}

// ---------------------------------------------------------------------------
extern "C" void kernel_launch(void* const* d_in, const int* in_sizes, int n_in,
                              void* d_out, int out_size) {
    const float* features = (const float*)d_in[0];
    const int*   node     = (const int*)d_in[1];
    const int*   neigh    = (const int*)d_in[2];
    const float* kern0    = (const float*)d_in[3];
    const float* kern1    = (const float*)d_in[4];
    const float* aw       = (const float*)d_in[5];
    const float* nw       = (const float*)d_in[6];
    float*       out      = (float*)d_out;

    int B = in_sizes[1];
    if (B > MAXB) B = MAXB;

    const int prep_smem = (D * D + D) * sizeof(float);       // ~66 KB
    cudaFuncSetAttribute(prep_kernel, cudaFuncAttributeMaxDynamicSharedMemorySize, prep_smem);
    prep_kernel<<<D, D, prep_smem>>>(kern0, kern1, aw, nw);

    attn_kernel<<<B, D>>>(features, node, neigh, B);

    const int gemm_smem = (D * D + D * 8) * sizeof(float);   // 68 KB
    cudaFuncSetAttribute(out_gemm, cudaFuncAttributeMaxDynamicSharedMemorySize, gemm_smem);
    out_gemm<<<444, D, gemm_smem>>>(out, B);
}